// round 1
// baseline (speedup 1.0000x reference)
#include <cuda_runtime.h>
#include <cuda_bf16.h>
#include <math_constants.h>

// Problem constants (fixed by reference): B=2, S=2048, E=1024, H=16, D=64
#define BSZ   2
#define SEQ   2048
#define EMB   1024
#define NHEAD 16
#define HDIM  64
#define ROWS  (BSZ * SEQ)          // 4096
#define QKV_N (3 * EMB)            // 3072

// Scratch (allocation-free rule: __device__ globals)
static __device__ float g_qkv[ROWS * QKV_N];   // [4096, 3072]
static __device__ float g_attn[ROWS * EMB];    // [4096, 1024]

// ---------------------------------------------------------------------------
// Packed f32x2 helpers (Blackwell FFMA2 — ptxas will not fuse these itself)
// ---------------------------------------------------------------------------
union F4U { float4 f4; unsigned long long u[2]; float f[4]; };
union F2U { float2 f2; unsigned long long u;    float f[2]; };

__device__ __forceinline__ unsigned long long pack2(float x, float y) {
    unsigned long long r;
    asm("mov.b64 %0, {%1, %2};" : "=l"(r) : "f"(x), "f"(y));
    return r;
}
__device__ __forceinline__ void fma2(unsigned long long& c,
                                     unsigned long long a,
                                     unsigned long long b) {
    asm("fma.rn.f32x2 %0, %1, %2, %0;" : "+l"(c) : "l"(a), "l"(b));
}
__device__ __forceinline__ void mul2(unsigned long long& c, unsigned long long a) {
    asm("mul.rn.f32x2 %0, %0, %1;" : "+l"(c) : "l"(a));
}
__device__ __forceinline__ float2 unpack2(unsigned long long v) {
    F2U t; t.u = v; return t.f2;
}

// ---------------------------------------------------------------------------
// GEMM + bias: C[M,N] = A[M,K] @ B[K,N] + bias[N]
// 64x64 tile, BK=16, 256 threads, 4x4 per thread, packed FFMA2 accumulators.
// M,N,K all multiples of tile sizes for this problem (no bounds checks).
// ---------------------------------------------------------------------------
__global__ void __launch_bounds__(256)
gemm_bias_kernel(const float* __restrict__ A, const float* __restrict__ B,
                 const float* __restrict__ bias, float* __restrict__ C,
                 int M, int N, int K)
{
    __shared__ float As[16][68];   // transposed A tile, padded (16B-aligned rows)
    __shared__ float Bs[16][64];

    const int tid = threadIdx.x;
    const int tx = tid & 15;       // 0..15 -> 4 output cols each
    const int ty = tid >> 4;       // 0..15 -> 4 output rows each
    const int row0 = blockIdx.y * 64;
    const int col0 = blockIdx.x * 64;

    // load mapping
    const int arow = tid >> 2;            // 0..63
    const int acol = (tid & 3) << 2;      // 0,4,8,12
    const int brow = tid >> 4;            // 0..15
    const int bcol = (tid & 15) << 2;     // 0..60

    const float* Ap = A + (size_t)(row0 + arow) * K + acol;
    const float* Bp = B + (size_t)brow * N + col0 + bcol;

    unsigned long long acc[4][2];
#pragma unroll
    for (int i = 0; i < 4; i++) { acc[i][0] = 0ull; acc[i][1] = 0ull; }

    for (int k0 = 0; k0 < K; k0 += 16) {
        float4 av = *(const float4*)Ap;  Ap += 16;
        As[acol + 0][arow] = av.x;
        As[acol + 1][arow] = av.y;
        As[acol + 2][arow] = av.z;
        As[acol + 3][arow] = av.w;
        *(float4*)&Bs[brow][bcol] = *(const float4*)Bp;  Bp += (size_t)16 * N;
        __syncthreads();

#pragma unroll
        for (int k = 0; k < 16; k++) {
            F4U a; a.f4 = *(const float4*)&As[k][ty << 2];
            F4U b; b.f4 = *(const float4*)&Bs[k][tx << 2];
#pragma unroll
            for (int i = 0; i < 4; i++) {
                unsigned long long ap = pack2(a.f[i], a.f[i]);
                fma2(acc[i][0], ap, b.u[0]);
                fma2(acc[i][1], ap, b.u[1]);
            }
        }
        __syncthreads();
    }

    const int crow = row0 + (ty << 2);
    const int ccol = col0 + (tx << 2);
    float4 bv = *(const float4*)&bias[ccol];
#pragma unroll
    for (int i = 0; i < 4; i++) {
        float2 p0 = unpack2(acc[i][0]);
        float2 p1 = unpack2(acc[i][1]);
        float4 out;
        out.x = p0.x + bv.x;
        out.y = p0.y + bv.y;
        out.z = p1.x + bv.z;
        out.w = p1.y + bv.w;
        *(float4*)&C[(size_t)(crow + i) * N + ccol] = out;
    }
}

// ---------------------------------------------------------------------------
// Flash attention (non-causal, sm_scale = 1/8):
// grid = (SEQ/128, NHEAD, BSZ), 128 threads, 1 thread = 1 query row.
// q and O accumulator in registers (packed u64), K/V tiles (64x64) + score
// staging buffer in dynamic smem.
// qkv layout: row (b*SEQ+s) of g_qkv: [q(0..1023) | k(1024..2047) | v(2048..3071)]
// ---------------------------------------------------------------------------
#define QT 128
#define KT 64
#define ATTN_SMEM_FLOATS (2 * KT * HDIM + QT * (KT + 1))
#define ATTN_SMEM_BYTES  (ATTN_SMEM_FLOATS * 4)   // 66048 B

__global__ void __launch_bounds__(128)
attn_kernel(const float* __restrict__ qkv, float* __restrict__ out)
{
    extern __shared__ float sh[];
    float* Ks = sh;                  // [KT][HDIM]
    float* Vs = sh + KT * HDIM;      // [KT][HDIM]
    float* Ss = sh + 2 * KT * HDIM;  // [QT][KT+1]

    const int r = threadIdx.x;                 // query row within tile
    const int h = blockIdx.y;
    const int b = blockIdx.z;
    const int qrow = blockIdx.x * QT + r;

    // load q row, pre-scaled by sm_scale = 0.125
    const float* qp = qkv + (size_t)(b * SEQ + qrow) * QKV_N + h * HDIM;
    unsigned long long q2[32];
#pragma unroll
    for (int i = 0; i < 16; i++) {
        F4U t; t.f4 = *(const float4*)(qp + i * 4);
        t.f[0] *= 0.125f; t.f[1] *= 0.125f; t.f[2] *= 0.125f; t.f[3] *= 0.125f;
        q2[2 * i + 0] = t.u[0];
        q2[2 * i + 1] = t.u[1];
    }

    unsigned long long o2[32];
#pragma unroll
    for (int i = 0; i < 32; i++) o2[i] = 0ull;
    float m = -CUDART_INF_F;
    float l = 0.0f;
    float* srow = Ss + r * (KT + 1);

    for (int kt = 0; kt < SEQ / KT; kt++) {
        // cooperative load of K and V tiles (coalesced: 16 threads per 64-float row)
        const float* kbase = qkv + (size_t)(b * SEQ + kt * KT) * QKV_N + EMB + h * HDIM;
        const float* vbase = kbase + EMB;
#pragma unroll
        for (int it = 0; it < 8; it++) {
            int lin = it * 512 + r * 4;
            int row = lin >> 6, col = lin & 63;
            *(float4*)&Ks[row * HDIM + col] = *(const float4*)(kbase + (size_t)row * QKV_N + col);
            *(float4*)&Vs[row * HDIM + col] = *(const float4*)(vbase + (size_t)row * QKV_N + col);
        }
        __syncthreads();

        // scores: s_j = q . k_j  (4 independent packed accumulators per j)
        float mt = -CUDART_INF_F;
        for (int j = 0; j < KT; j++) {
            const float4* kk = (const float4*)&Ks[j * HDIM];
            unsigned long long a0 = 0ull, a1 = 0ull, a2 = 0ull, a3 = 0ull;
#pragma unroll
            for (int d4 = 0; d4 < 16; d4 += 2) {
                F4U k0; k0.f4 = kk[d4];
                F4U k1; k1.f4 = kk[d4 + 1];
                fma2(a0, q2[2 * d4 + 0], k0.u[0]);
                fma2(a1, q2[2 * d4 + 1], k0.u[1]);
                fma2(a2, q2[2 * d4 + 2], k1.u[0]);
                fma2(a3, q2[2 * d4 + 3], k1.u[1]);
            }
            float2 p0 = unpack2(a0), p1 = unpack2(a1), p2 = unpack2(a2), p3 = unpack2(a3);
            float s = (p0.x + p0.y) + (p1.x + p1.y) + (p2.x + p2.y) + (p3.x + p3.y);
            srow[j] = s;
            mt = fmaxf(mt, s);
        }

        // online softmax update
        float mnew = fmaxf(m, mt);
        float alpha = __expf(m - mnew);   // first tile: exp(-inf) = 0
        float lsum = 0.0f;
#pragma unroll 8
        for (int j = 0; j < KT; j++) {
            float p = __expf(srow[j] - mnew);
            lsum += p;
            srow[j] = p;
        }
        l = l * alpha + lsum;

        unsigned long long al2 = pack2(alpha, alpha);
#pragma unroll
        for (int dd = 0; dd < 32; dd++) mul2(o2[dd], al2);

        // O += P @ V
        for (int j = 0; j < KT; j++) {
            unsigned long long pp = pack2(srow[j], srow[j]);
            const float4* vv = (const float4*)&Vs[j * HDIM];
#pragma unroll
            for (int d4 = 0; d4 < 16; d4++) {
                F4U v; v.f4 = vv[d4];
                fma2(o2[2 * d4 + 0], pp, v.u[0]);
                fma2(o2[2 * d4 + 1], pp, v.u[1]);
            }
        }

        m = mnew;
        __syncthreads();
    }

    // normalize and write out [B,S,H,D] == [B,S,E]
    float inv = 1.0f / l;
    unsigned long long inv2 = pack2(inv, inv);
    float* op = out + (size_t)(b * SEQ + qrow) * EMB + h * HDIM;
#pragma unroll
    for (int d4 = 0; d4 < 16; d4++) {
        mul2(o2[2 * d4 + 0], inv2);
        mul2(o2[2 * d4 + 1], inv2);
        F4U t;
        t.u[0] = o2[2 * d4 + 0];
        t.u[1] = o2[2 * d4 + 1];
        *(float4*)(op + d4 * 4) = t.f4;
    }
}

// ---------------------------------------------------------------------------
// launch
// ---------------------------------------------------------------------------
extern "C" void kernel_launch(void* const* d_in, const int* in_sizes, int n_in,
                              void* d_out, int out_size)
{
    const float* x     = (const float*)d_in[0];  // [2,2048,1024]
    const float* W_qkv = (const float*)d_in[1];  // [1024,3072]
    const float* b_qkv = (const float*)d_in[2];  // [3072]
    const float* W_out = (const float*)d_in[3];  // [1024,1024]
    const float* b_out = (const float*)d_in[4];  // [1024]
    float* out = (float*)d_out;                  // [2,2048,1024]

    float* qkv  = nullptr;
    float* attn = nullptr;
    cudaGetSymbolAddress((void**)&qkv,  g_qkv);
    cudaGetSymbolAddress((void**)&attn, g_attn);

    // 1) QKV projection: [4096,1024] @ [1024,3072] + b
    gemm_bias_kernel<<<dim3(QKV_N / 64, ROWS / 64), 256>>>(
        x, W_qkv, b_qkv, qkv, ROWS, QKV_N, EMB);

    // 2) flash attention
    cudaFuncSetAttribute(attn_kernel,
                         cudaFuncAttributeMaxDynamicSharedMemorySize,
                         ATTN_SMEM_BYTES);
    attn_kernel<<<dim3(SEQ / QT, NHEAD, BSZ), 128, ATTN_SMEM_BYTES>>>(qkv, attn);

    // 3) output projection: [4096,1024] @ [1024,1024] + b
    gemm_bias_kernel<<<dim3(EMB / 64, ROWS / 64), 256>>>(
        attn, W_out, b_out, out, ROWS, EMB, EMB);
}

// round 4
// speedup vs baseline: 1.3985x; 1.3985x over previous
#include <cuda_runtime.h>
#include <cuda_bf16.h>
#include <math_constants.h>
#include <cstdint>

// Problem constants (fixed by reference): B=2, S=2048, E=1024, H=16, D=64
#define BSZ   2
#define SEQ   2048
#define EMB   1024
#define NHEAD 16
#define HDIM  64
#define ROWS  (BSZ * SEQ)          // 4096
#define QKV_N (3 * EMB)            // 3072

// Scratch (allocation-free rule: __device__ globals)
static __device__ float g_qkv[ROWS * QKV_N];    // [4096, 3072]
static __device__ float g_attn[ROWS * EMB];     // [4096, 1024]  (tf32-rounded)
static __device__ float g_xc[ROWS * EMB];       // x, tf32-rounded
static __device__ float g_wqt[QKV_N * EMB];     // W_qkv^T [3072,1024], tf32-rounded
static __device__ float g_wot[EMB * EMB];       // W_out^T [1024,1024], tf32-rounded

// ---------------------------------------------------------------------------
// helpers
// ---------------------------------------------------------------------------
__device__ __forceinline__ uint32_t smem_to_u32(const void* p) {
    uint32_t a;
    asm("{ .reg .u64 t; cvta.to.shared.u64 t, %1; cvt.u32.u64 %0, t; }" : "=r"(a) : "l"(p));
    return a;
}
// cvt.rna.tf32.f32 writes a .b32 destination (tf32 is a bit pattern)
__device__ __forceinline__ float rna_tf32(float x) {
    uint32_t r;
    asm("cvt.rna.tf32.f32 %0, %1;" : "=r"(r) : "f"(x));
    return __uint_as_float(r);
}
__device__ __forceinline__ void cp16(uint32_t d, const void* s) {
    asm volatile("cp.async.cg.shared.global [%0], [%1], 16;" :: "r"(d), "l"(s));
}
// warp-level tf32 MMA (sm_80+; works at compute_100)
__device__ __forceinline__ void mma_tf32(float* c, const uint32_t* a, const uint32_t* b) {
    asm volatile("mma.sync.aligned.m16n8k8.row.col.f32.tf32.tf32.f32 "
                 "{%0,%1,%2,%3}, {%4,%5,%6,%7}, {%8,%9}, {%0,%1,%2,%3};"
                 : "+f"(c[0]), "+f"(c[1]), "+f"(c[2]), "+f"(c[3])
                 : "r"(a[0]), "r"(a[1]), "r"(a[2]), "r"(a[3]),
                   "r"(b[0]), "r"(b[1]));
}

// ---------------------------------------------------------------------------
// Prep kernels: tf32-rna rounding (+ transpose for weights)
// ---------------------------------------------------------------------------
__global__ void cvt_rna_kernel(const float4* __restrict__ in, float4* __restrict__ out, int n4) {
    int i = blockIdx.x * blockDim.x + threadIdx.x;
    if (i < n4) {
        float4 v = in[i];
        v.x = rna_tf32(v.x); v.y = rna_tf32(v.y);
        v.z = rna_tf32(v.z); v.w = rna_tf32(v.w);
        out[i] = v;
    }
}

// in: [R,C] row-major  ->  out: [C,R] row-major, rna-rounded
__global__ void transpose_cvt_kernel(const float* __restrict__ in, float* __restrict__ out,
                                     int R, int C) {
    __shared__ float t[32][33];
    int c0 = blockIdx.x * 32, r0 = blockIdx.y * 32;
    int tx = threadIdx.x, ty = threadIdx.y;
#pragma unroll
    for (int i = 0; i < 32; i += 8)
        t[ty + i][tx] = in[(size_t)(r0 + ty + i) * C + c0 + tx];
    __syncthreads();
#pragma unroll
    for (int i = 0; i < 32; i += 8)
        out[(size_t)(c0 + ty + i) * R + r0 + tx] = rna_tf32(t[tx][ty + i]);
}

// ---------------------------------------------------------------------------
// tf32 warp-MMA GEMM + bias: C[M,N] = A[M,K] @ Bt[N,K]^T + bias[N]
// CTA tile 128x128, 8 warps (2x4), each warp 64x32 (4x4 m16n8k8 tiles).
// K-step 32, cp.async double buffer, smem row stride 36 floats (conflict-free:
// bank = (4*row + col) mod 32, all 32 lanes distinct for the fragment pattern).
// A, Bt pre-rounded to tf32. grid = (N/128, M/128), 256 threads.
// ---------------------------------------------------------------------------
#define RS        36                       // smem row stride in floats
#define ASTG      (128 * RS)               // words per operand stage (4608)
#define STG_WORDS (2 * ASTG)               // A + B per stage (9216)
#define GK_DSMEM  (2 * STG_WORDS * 4)      // 73728 B

__global__ void __launch_bounds__(256, 2)
gemm_tc_kernel(const float* __restrict__ A, const float* __restrict__ Bt,
               const float* __restrict__ bias, float* __restrict__ C,
               int K, int N)
{
    extern __shared__ float sh[];
    const int tid = threadIdx.x;
    const int wid = tid >> 5, lane = tid & 31;
    const int g = lane >> 2, t = lane & 3;
    const int row0 = blockIdx.y * 128;
    const int col0 = blockIdx.x * 128;
    const int mbase = (wid & 1) * 64;
    const int nbase = (wid >> 1) * 32;
    const int NK = K / 32;
    const uint32_t sb = smem_to_u32(sh);

    auto load_stage = [&](int j, int p) {
        const float* Ab = A + (size_t)row0 * K + j * 32;
        const float* Bb = Bt + (size_t)col0 * K + j * 32;
        uint32_t abase = sb + p * (STG_WORDS * 4);
        uint32_t bbase = abase + ASTG * 4;
#pragma unroll
        for (int i = 0; i < 4; i++) {
            int c = tid + 256 * i;
            int row = c >> 3, c8 = c & 7;
            cp16(abase + row * (RS * 4) + c8 * 16, Ab + (size_t)row * K + c8 * 4);
            cp16(bbase + row * (RS * 4) + c8 * 16, Bb + (size_t)row * K + c8 * 4);
        }
        asm volatile("cp.async.commit_group;");
    };

    float acc[4][4][4];
#pragma unroll
    for (int mt = 0; mt < 4; mt++)
#pragma unroll
        for (int nt = 0; nt < 4; nt++)
#pragma unroll
            for (int i = 0; i < 4; i++) acc[mt][nt][i] = 0.0f;

    load_stage(0, 0);
    load_stage(1, 1);

    for (int j = 0; j < NK; j++) {
        const int p = j & 1;
        asm volatile("cp.async.wait_group 1;");
        __syncthreads();

        const float* As = sh + p * STG_WORDS;
        const float* Bs = As + ASTG;
#pragma unroll
        for (int ks = 0; ks < 4; ks++) {
            const int kc = ks * 8;
            uint32_t a[4][4], b[4][2];
#pragma unroll
            for (int mt = 0; mt < 4; mt++) {
                int r0 = (mbase + mt * 16 + g) * RS + kc + t;
                a[mt][0] = __float_as_uint(As[r0]);
                a[mt][1] = __float_as_uint(As[r0 + 8 * RS]);
                a[mt][2] = __float_as_uint(As[r0 + 4]);
                a[mt][3] = __float_as_uint(As[r0 + 8 * RS + 4]);
            }
#pragma unroll
            for (int nt = 0; nt < 4; nt++) {
                int r0 = (nbase + nt * 8 + g) * RS + kc + t;
                b[nt][0] = __float_as_uint(Bs[r0]);
                b[nt][1] = __float_as_uint(Bs[r0 + 4]);
            }
#pragma unroll
            for (int mt = 0; mt < 4; mt++)
#pragma unroll
                for (int nt = 0; nt < 4; nt++)
                    mma_tf32(acc[mt][nt], a[mt], b[nt]);
        }
        __syncthreads();
        if (j + 2 < NK) load_stage(j + 2, p);
        else asm volatile("cp.async.commit_group;");   // keep group count in step
    }

    // epilogue: c0/c1 -> (row, col..col+1), c2/c3 -> (row+8, ...)
#pragma unroll
    for (int mt = 0; mt < 4; mt++) {
        const int row = row0 + mbase + mt * 16 + g;
#pragma unroll
        for (int nt = 0; nt < 4; nt++) {
            const int col = col0 + nbase + nt * 8 + t * 2;
            const float b0 = bias[col], b1 = bias[col + 1];
            float2 v0 = { acc[mt][nt][0] + b0, acc[mt][nt][1] + b1 };
            float2 v1 = { acc[mt][nt][2] + b0, acc[mt][nt][3] + b1 };
            *(float2*)&C[(size_t)row * N + col] = v0;
            *(float2*)&C[(size_t)(row + 8) * N + col] = v1;
        }
    }
}

// ---------------------------------------------------------------------------
// Packed f32x2 helpers for the (unchanged) attention kernel
// ---------------------------------------------------------------------------
union F4U { float4 f4; unsigned long long u[2]; float f[4]; };
union F2U { float2 f2; unsigned long long u;    float f[2]; };

__device__ __forceinline__ unsigned long long pack2(float x, float y) {
    unsigned long long r;
    asm("mov.b64 %0, {%1, %2};" : "=l"(r) : "f"(x), "f"(y));
    return r;
}
__device__ __forceinline__ void fma2(unsigned long long& c, unsigned long long a, unsigned long long b) {
    asm("fma.rn.f32x2 %0, %1, %2, %0;" : "+l"(c) : "l"(a), "l"(b));
}
__device__ __forceinline__ void mul2(unsigned long long& c, unsigned long long a) {
    asm("mul.rn.f32x2 %0, %0, %1;" : "+l"(c) : "l"(a));
}
__device__ __forceinline__ float2 unpack2(unsigned long long v) {
    F2U t; t.u = v; return t.f2;
}

// ---------------------------------------------------------------------------
// Flash attention (non-causal, sm_scale = 1/8). Output rounded to tf32-rna
// so the out-projection's tensor-core input is exactly representable.
// ---------------------------------------------------------------------------
#define QT 128
#define KT 64
#define ATTN_SMEM_FLOATS (2 * KT * HDIM + QT * (KT + 1))
#define ATTN_SMEM_BYTES  (ATTN_SMEM_FLOATS * 4)   // 66048 B

__global__ void __launch_bounds__(128)
attn_kernel(const float* __restrict__ qkv, float* __restrict__ out)
{
    extern __shared__ float sh[];
    float* Ks = sh;
    float* Vs = sh + KT * HDIM;
    float* Ss = sh + 2 * KT * HDIM;

    const int r = threadIdx.x;
    const int h = blockIdx.y;
    const int b = blockIdx.z;
    const int qrow = blockIdx.x * QT + r;

    const float* qp = qkv + (size_t)(b * SEQ + qrow) * QKV_N + h * HDIM;
    unsigned long long q2[32];
#pragma unroll
    for (int i = 0; i < 16; i++) {
        F4U t; t.f4 = *(const float4*)(qp + i * 4);
        t.f[0] *= 0.125f; t.f[1] *= 0.125f; t.f[2] *= 0.125f; t.f[3] *= 0.125f;
        q2[2 * i + 0] = t.u[0];
        q2[2 * i + 1] = t.u[1];
    }

    unsigned long long o2[32];
#pragma unroll
    for (int i = 0; i < 32; i++) o2[i] = 0ull;
    float m = -CUDART_INF_F;
    float l = 0.0f;
    float* srow = Ss + r * (KT + 1);

    for (int kt = 0; kt < SEQ / KT; kt++) {
        const float* kbase = qkv + (size_t)(b * SEQ + kt * KT) * QKV_N + EMB + h * HDIM;
        const float* vbase = kbase + EMB;
#pragma unroll
        for (int it = 0; it < 8; it++) {
            int lin = it * 512 + r * 4;
            int row = lin >> 6, col = lin & 63;
            *(float4*)&Ks[row * HDIM + col] = *(const float4*)(kbase + (size_t)row * QKV_N + col);
            *(float4*)&Vs[row * HDIM + col] = *(const float4*)(vbase + (size_t)row * QKV_N + col);
        }
        __syncthreads();

        float mt = -CUDART_INF_F;
        for (int j = 0; j < KT; j++) {
            const float4* kk = (const float4*)&Ks[j * HDIM];
            unsigned long long a0 = 0ull, a1 = 0ull, a2 = 0ull, a3 = 0ull;
#pragma unroll
            for (int d4 = 0; d4 < 16; d4 += 2) {
                F4U k0; k0.f4 = kk[d4];
                F4U k1; k1.f4 = kk[d4 + 1];
                fma2(a0, q2[2 * d4 + 0], k0.u[0]);
                fma2(a1, q2[2 * d4 + 1], k0.u[1]);
                fma2(a2, q2[2 * d4 + 2], k1.u[0]);
                fma2(a3, q2[2 * d4 + 3], k1.u[1]);
            }
            float2 p0 = unpack2(a0), p1 = unpack2(a1), p2 = unpack2(a2), p3 = unpack2(a3);
            float s = (p0.x + p0.y) + (p1.x + p1.y) + (p2.x + p2.y) + (p3.x + p3.y);
            srow[j] = s;
            mt = fmaxf(mt, s);
        }

        float mnew = fmaxf(m, mt);
        float alpha = __expf(m - mnew);
        float lsum = 0.0f;
#pragma unroll 8
        for (int j = 0; j < KT; j++) {
            float p = __expf(srow[j] - mnew);
            lsum += p;
            srow[j] = p;
        }
        l = l * alpha + lsum;

        unsigned long long al2 = pack2(alpha, alpha);
#pragma unroll
        for (int dd = 0; dd < 32; dd++) mul2(o2[dd], al2);

        for (int j = 0; j < KT; j++) {
            unsigned long long pp = pack2(srow[j], srow[j]);
            const float4* vv = (const float4*)&Vs[j * HDIM];
#pragma unroll
            for (int d4 = 0; d4 < 16; d4++) {
                F4U v; v.f4 = vv[d4];
                fma2(o2[2 * d4 + 0], pp, v.u[0]);
                fma2(o2[2 * d4 + 1], pp, v.u[1]);
            }
        }

        m = mnew;
        __syncthreads();
    }

    float inv = 1.0f / l;
    unsigned long long inv2 = pack2(inv, inv);
    float* op = out + (size_t)(b * SEQ + qrow) * EMB + h * HDIM;
#pragma unroll
    for (int d4 = 0; d4 < 16; d4++) {
        mul2(o2[2 * d4 + 0], inv2);
        mul2(o2[2 * d4 + 1], inv2);
        F4U t;
        t.u[0] = o2[2 * d4 + 0];
        t.u[1] = o2[2 * d4 + 1];
        t.f[0] = rna_tf32(t.f[0]); t.f[1] = rna_tf32(t.f[1]);
        t.f[2] = rna_tf32(t.f[2]); t.f[3] = rna_tf32(t.f[3]);
        *(float4*)(op + d4 * 4) = t.f4;
    }
}

// ---------------------------------------------------------------------------
// launch
// ---------------------------------------------------------------------------
extern "C" void kernel_launch(void* const* d_in, const int* in_sizes, int n_in,
                              void* d_out, int out_size)
{
    const float* x     = (const float*)d_in[0];  // [2,2048,1024]
    const float* W_qkv = (const float*)d_in[1];  // [1024,3072]
    const float* b_qkv = (const float*)d_in[2];  // [3072]
    const float* W_out = (const float*)d_in[3];  // [1024,1024]
    const float* b_out = (const float*)d_in[4];  // [1024]
    float* out = (float*)d_out;                  // [2,2048,1024]

    float *qkv, *attn, *xc, *wqt, *wot;
    cudaGetSymbolAddress((void**)&qkv,  g_qkv);
    cudaGetSymbolAddress((void**)&attn, g_attn);
    cudaGetSymbolAddress((void**)&xc,   g_xc);
    cudaGetSymbolAddress((void**)&wqt,  g_wqt);
    cudaGetSymbolAddress((void**)&wot,  g_wot);

    // 0) prep: tf32-rna rounding of x, transposed+rounded weights
    cvt_rna_kernel<<<(ROWS * EMB / 4 + 255) / 256, 256>>>((const float4*)x, (float4*)xc, ROWS * EMB / 4);
    transpose_cvt_kernel<<<dim3(QKV_N / 32, EMB / 32), dim3(32, 8)>>>(W_qkv, wqt, EMB, QKV_N);
    transpose_cvt_kernel<<<dim3(EMB / 32, EMB / 32), dim3(32, 8)>>>(W_out, wot, EMB, EMB);

    cudaFuncSetAttribute(gemm_tc_kernel,
                         cudaFuncAttributeMaxDynamicSharedMemorySize, GK_DSMEM);

    // 1) QKV projection: [4096,1024] @ [1024,3072] + b   (tensor cores, mma.sync tf32)
    gemm_tc_kernel<<<dim3(QKV_N / 128, ROWS / 128), 256, GK_DSMEM>>>(
        xc, wqt, b_qkv, qkv, EMB, QKV_N);

    // 2) flash attention (FFMA2; output tf32-rounded)
    cudaFuncSetAttribute(attn_kernel,
                         cudaFuncAttributeMaxDynamicSharedMemorySize, ATTN_SMEM_BYTES);
    attn_kernel<<<dim3(SEQ / QT, NHEAD, BSZ), 128, ATTN_SMEM_BYTES>>>(qkv, attn);

    // 3) output projection: [4096,1024] @ [1024,1024] + b   (tensor cores, mma.sync tf32)
    gemm_tc_kernel<<<dim3(EMB / 128, ROWS / 128), 256, GK_DSMEM>>>(
        attn, wot, b_out, out, EMB, EMB);
}

// round 6
// speedup vs baseline: 3.8313x; 2.7396x over previous
#include <cuda_runtime.h>
#include <cuda_bf16.h>
#include <math_constants.h>
#include <cstdint>

// Problem constants (fixed by reference): B=2, S=2048, E=1024, H=16, D=64
#define BSZ   2
#define SEQ   2048
#define EMB   1024
#define NHEAD 16
#define HDIM  64
#define ROWS  (BSZ * SEQ)          // 4096
#define QKV_N (3 * EMB)            // 3072

// Scratch (allocation-free rule: __device__ globals)
static __device__ float g_qkv[ROWS * QKV_N];    // [4096, 3072] (tf32-rounded)
static __device__ float g_attn[ROWS * EMB];     // [4096, 1024] (tf32-rounded)
static __device__ float g_xc[ROWS * EMB];       // x, tf32-rounded
static __device__ float g_wqt[QKV_N * EMB];     // W_qkv^T [3072,1024], tf32-rounded
static __device__ float g_wot[EMB * EMB];       // W_out^T [1024,1024], tf32-rounded

// ---------------------------------------------------------------------------
// helpers
// ---------------------------------------------------------------------------
__device__ __forceinline__ uint32_t smem_to_u32(const void* p) {
    uint32_t a;
    asm("{ .reg .u64 t; cvta.to.shared.u64 t, %1; cvt.u32.u64 %0, t; }" : "=r"(a) : "l"(p));
    return a;
}
// cvt.rna.tf32.f32 writes a .b32 destination (tf32 is a bit pattern)
__device__ __forceinline__ float rna_tf32(float x) {
    uint32_t r;
    asm("cvt.rna.tf32.f32 %0, %1;" : "=r"(r) : "f"(x));
    return __uint_as_float(r);
}
__device__ __forceinline__ void cp16(uint32_t d, const void* s) {
    asm volatile("cp.async.cg.shared.global [%0], [%1], 16;" :: "r"(d), "l"(s));
}
// warp-level tf32 MMA (sm_80+; works at compute_100)
__device__ __forceinline__ void mma_tf32(float* c, const uint32_t* a, const uint32_t* b) {
    asm volatile("mma.sync.aligned.m16n8k8.row.col.f32.tf32.tf32.f32 "
                 "{%0,%1,%2,%3}, {%4,%5,%6,%7}, {%8,%9}, {%0,%1,%2,%3};"
                 : "+f"(c[0]), "+f"(c[1]), "+f"(c[2]), "+f"(c[3])
                 : "r"(a[0]), "r"(a[1]), "r"(a[2]), "r"(a[3]),
                   "r"(b[0]), "r"(b[1]));
}

// ---------------------------------------------------------------------------
// Prep kernels: tf32-rna rounding (+ transpose for weights)
// ---------------------------------------------------------------------------
__global__ void cvt_rna_kernel(const float4* __restrict__ in, float4* __restrict__ out, int n4) {
    int i = blockIdx.x * blockDim.x + threadIdx.x;
    if (i < n4) {
        float4 v = in[i];
        v.x = rna_tf32(v.x); v.y = rna_tf32(v.y);
        v.z = rna_tf32(v.z); v.w = rna_tf32(v.w);
        out[i] = v;
    }
}

// in: [R,C] row-major  ->  out: [C,R] row-major, rna-rounded
__global__ void transpose_cvt_kernel(const float* __restrict__ in, float* __restrict__ out,
                                     int R, int C) {
    __shared__ float t[32][33];
    int c0 = blockIdx.x * 32, r0 = blockIdx.y * 32;
    int tx = threadIdx.x, ty = threadIdx.y;
#pragma unroll
    for (int i = 0; i < 32; i += 8)
        t[ty + i][tx] = in[(size_t)(r0 + ty + i) * C + c0 + tx];
    __syncthreads();
#pragma unroll
    for (int i = 0; i < 32; i += 8)
        out[(size_t)(c0 + ty + i) * R + r0 + tx] = rna_tf32(t[tx][ty + i]);
}

// ---------------------------------------------------------------------------
// tf32 warp-MMA GEMM + bias: C[M,N] = A[M,K] @ Bt[N,K]^T + bias[N]
// CTA tile 128x128, 8 warps (2x4), each warp 64x32 (4x4 m16n8k8 tiles).
// ROUND: rna-round the output (for tensors feeding later tf32 MMAs).
// ---------------------------------------------------------------------------
#define RS        36                       // smem row stride in floats
#define ASTG      (128 * RS)               // words per operand stage (4608)
#define STG_WORDS (2 * ASTG)               // A + B per stage (9216)
#define GK_DSMEM  (2 * STG_WORDS * 4)      // 73728 B

template <bool ROUND>
__global__ void __launch_bounds__(256, 2)
gemm_tc_kernel(const float* __restrict__ A, const float* __restrict__ Bt,
               const float* __restrict__ bias, float* __restrict__ C,
               int K, int N)
{
    extern __shared__ float sh[];
    const int tid = threadIdx.x;
    const int wid = tid >> 5, lane = tid & 31;
    const int g = lane >> 2, t = lane & 3;
    const int row0 = blockIdx.y * 128;
    const int col0 = blockIdx.x * 128;
    const int mbase = (wid & 1) * 64;
    const int nbase = (wid >> 1) * 32;
    const int NK = K / 32;
    const uint32_t sb = smem_to_u32(sh);

    auto load_stage = [&](int j, int p) {
        const float* Ab = A + (size_t)row0 * K + j * 32;
        const float* Bb = Bt + (size_t)col0 * K + j * 32;
        uint32_t abase = sb + p * (STG_WORDS * 4);
        uint32_t bbase = abase + ASTG * 4;
#pragma unroll
        for (int i = 0; i < 4; i++) {
            int c = tid + 256 * i;
            int row = c >> 3, c8 = c & 7;
            cp16(abase + row * (RS * 4) + c8 * 16, Ab + (size_t)row * K + c8 * 4);
            cp16(bbase + row * (RS * 4) + c8 * 16, Bb + (size_t)row * K + c8 * 4);
        }
        asm volatile("cp.async.commit_group;");
    };

    float acc[4][4][4];
#pragma unroll
    for (int mt = 0; mt < 4; mt++)
#pragma unroll
        for (int nt = 0; nt < 4; nt++)
#pragma unroll
            for (int i = 0; i < 4; i++) acc[mt][nt][i] = 0.0f;

    load_stage(0, 0);
    load_stage(1, 1);

    for (int j = 0; j < NK; j++) {
        const int p = j & 1;
        asm volatile("cp.async.wait_group 1;");
        __syncthreads();

        const float* As = sh + p * STG_WORDS;
        const float* Bs = As + ASTG;
#pragma unroll
        for (int ks = 0; ks < 4; ks++) {
            const int kc = ks * 8;
            uint32_t a[4][4], b[4][2];
#pragma unroll
            for (int mt = 0; mt < 4; mt++) {
                int r0 = (mbase + mt * 16 + g) * RS + kc + t;
                a[mt][0] = __float_as_uint(As[r0]);
                a[mt][1] = __float_as_uint(As[r0 + 8 * RS]);
                a[mt][2] = __float_as_uint(As[r0 + 4]);
                a[mt][3] = __float_as_uint(As[r0 + 8 * RS + 4]);
            }
#pragma unroll
            for (int nt = 0; nt < 4; nt++) {
                int r0 = (nbase + nt * 8 + g) * RS + kc + t;
                b[nt][0] = __float_as_uint(Bs[r0]);
                b[nt][1] = __float_as_uint(Bs[r0 + 4]);
            }
#pragma unroll
            for (int mt = 0; mt < 4; mt++)
#pragma unroll
                for (int nt = 0; nt < 4; nt++)
                    mma_tf32(acc[mt][nt], a[mt], b[nt]);
        }
        __syncthreads();
        if (j + 2 < NK) load_stage(j + 2, p);
        else asm volatile("cp.async.commit_group;");   // keep group count in step
    }

    // epilogue: c0/c1 -> (row, col..col+1), c2/c3 -> (row+8, ...)
#pragma unroll
    for (int mt = 0; mt < 4; mt++) {
        const int row = row0 + mbase + mt * 16 + g;
#pragma unroll
        for (int nt = 0; nt < 4; nt++) {
            const int col = col0 + nbase + nt * 8 + t * 2;
            const float b0 = bias[col], b1 = bias[col + 1];
            float2 v0, v1;
            if (ROUND) {
                v0 = { rna_tf32(acc[mt][nt][0] + b0), rna_tf32(acc[mt][nt][1] + b1) };
                v1 = { rna_tf32(acc[mt][nt][2] + b0), rna_tf32(acc[mt][nt][3] + b1) };
            } else {
                v0 = { acc[mt][nt][0] + b0, acc[mt][nt][1] + b1 };
                v1 = { acc[mt][nt][2] + b0, acc[mt][nt][3] + b1 };
            }
            *(float2*)&C[(size_t)row * N + col] = v0;
            *(float2*)&C[(size_t)(row + 8) * N + col] = v1;
        }
    }
}

// ---------------------------------------------------------------------------
// Tensor-core flash attention (non-causal, sm_scale = 1/8).
// CTA: 128 q-rows x one head; 8 warps, each owns 16 q-rows.
// K-tile 64 keys, cp.async double-buffered. All MMA inputs are tf32 patterns
// (qkv pre-rounded by the QKV GEMM epilogue; P rna-rounded before store).
// Output rna-rounded (feeds out-projection tf32 GEMM).
// ---------------------------------------------------------------------------
#define KTL    64
#define KS_STR 68     // fragment LDS bank pattern (4g+t) mod 32: conflict-free
#define VS_STR 72     // fragment LDS bank pattern (8t+g) mod 32: conflict-free
#define PS_STR 68
#define SM_K0  0
#define SM_K1  (64 * KS_STR)
#define SM_V0  (2 * 64 * KS_STR)
#define SM_V1  (SM_V0 + 64 * VS_STR)
#define SM_P   (SM_V0 + 2 * 64 * VS_STR)
#define ATTN_SMEM_FLOATS (SM_P + 128 * PS_STR)
#define ATTN_SMEM_BYTES  (ATTN_SMEM_FLOATS * 4)    // 106496 B

__global__ void __launch_bounds__(256, 1)
attn_tc_kernel(const float* __restrict__ qkv, float* __restrict__ out)
{
    extern __shared__ float sh[];
    const uint32_t sb = smem_to_u32(sh);
    const int tid = threadIdx.x, wid = tid >> 5, lane = tid & 31;
    const int g = lane >> 2, t = lane & 3;
    const int h = blockIdx.y, b = blockIdx.z;
    const int q0 = blockIdx.x * 128;
    const size_t rowbase = (size_t)(b * SEQ) * QKV_N;
    const float* qbase = qkv + rowbase + (size_t)q0 * QKV_N + h * HDIM;

    // stage Q[128,64] into the P buffer, build register fragments
    {
#pragma unroll
        for (int i = 0; i < 8; i++) {
            int c = tid + 256 * i;              // 2048 float4 chunks
            int row = c >> 4, c16 = c & 15;
            cp16(sb + (SM_P + row * PS_STR) * 4 + c16 * 16,
                 qbase + (size_t)row * QKV_N + c16 * 4);
        }
        asm volatile("cp.async.commit_group;");
        asm volatile("cp.async.wait_group 0;");
        __syncthreads();
    }
    float qf[8][4];
    {
        const float* Qs = sh + SM_P;
#pragma unroll
        for (int ks = 0; ks < 8; ks++) {
            int r0 = (wid * 16 + g) * PS_STR + ks * 8 + t;
            qf[ks][0] = Qs[r0] * 0.125f;                 // exact scale, stays tf32
            qf[ks][1] = Qs[r0 + 8 * PS_STR] * 0.125f;
            qf[ks][2] = Qs[r0 + 4] * 0.125f;
            qf[ks][3] = Qs[r0 + 8 * PS_STR + 4] * 0.125f;
        }
    }
    __syncthreads();

    float oacc[8][4];
#pragma unroll
    for (int nt = 0; nt < 8; nt++)
#pragma unroll
        for (int i = 0; i < 4; i++) oacc[nt][i] = 0.0f;
    float m0 = -CUDART_INF_F, m1 = -CUDART_INF_F, l0 = 0.0f, l1 = 0.0f;

    auto load_kv = [&](int kt2, int p) {
        const float* kb = qkv + rowbase + (size_t)(kt2 * KTL) * QKV_N + EMB + h * HDIM;
        const float* vb = kb + EMB;
        uint32_t kdst = sb + (p ? SM_K1 : SM_K0) * 4;
        uint32_t vdst = sb + (p ? SM_V1 : SM_V0) * 4;
#pragma unroll
        for (int i = 0; i < 4; i++) {
            int c = tid + 256 * i;              // 1024 float4 chunks each
            int row = c >> 4, c16 = c & 15;
            cp16(kdst + row * (KS_STR * 4) + c16 * 16, kb + (size_t)row * QKV_N + c16 * 4);
            cp16(vdst + row * (VS_STR * 4) + c16 * 16, vb + (size_t)row * QKV_N + c16 * 4);
        }
        asm volatile("cp.async.commit_group;");
    };

    load_kv(0, 0);
    load_kv(1, 1);

    float* Pw = sh + SM_P;
    const int prow0 = (wid * 16 + g) * PS_STR;
    const int prow1 = (wid * 16 + 8 + g) * PS_STR;

    for (int kt = 0; kt < SEQ / KTL; kt++) {
        const int p = kt & 1;
        asm volatile("cp.async.wait_group 1;");
        __syncthreads();
        const float* Ks = sh + (p ? SM_K1 : SM_K0);
        const float* Vs = sh + (p ? SM_V1 : SM_V0);

        // S = Q @ K^T   (per warp: 16 rows x 64 keys)
        float sacc[8][4];
#pragma unroll
        for (int nt = 0; nt < 8; nt++)
#pragma unroll
            for (int i = 0; i < 4; i++) sacc[nt][i] = 0.0f;
#pragma unroll
        for (int ks = 0; ks < 8; ks++) {
            const int kc = ks * 8;
            uint32_t a[4];
            a[0] = __float_as_uint(qf[ks][0]);
            a[1] = __float_as_uint(qf[ks][1]);
            a[2] = __float_as_uint(qf[ks][2]);
            a[3] = __float_as_uint(qf[ks][3]);
#pragma unroll
            for (int nt = 0; nt < 8; nt++) {
                uint32_t bb[2];
                int rb = (nt * 8 + g) * KS_STR + kc + t;
                bb[0] = __float_as_uint(Ks[rb]);
                bb[1] = __float_as_uint(Ks[rb + 4]);
                mma_tf32(sacc[nt], a, bb);
            }
        }

        // online softmax (rows g and g+8 of this warp's block)
        float mt0 = -CUDART_INF_F, mt1 = -CUDART_INF_F;
#pragma unroll
        for (int nt = 0; nt < 8; nt++) {
            mt0 = fmaxf(mt0, fmaxf(sacc[nt][0], sacc[nt][1]));
            mt1 = fmaxf(mt1, fmaxf(sacc[nt][2], sacc[nt][3]));
        }
        mt0 = fmaxf(mt0, __shfl_xor_sync(0xffffffffu, mt0, 1));
        mt0 = fmaxf(mt0, __shfl_xor_sync(0xffffffffu, mt0, 2));
        mt1 = fmaxf(mt1, __shfl_xor_sync(0xffffffffu, mt1, 1));
        mt1 = fmaxf(mt1, __shfl_xor_sync(0xffffffffu, mt1, 2));

        const float mn0 = fmaxf(m0, mt0), mn1 = fmaxf(m1, mt1);
        const float al0 = __expf(m0 - mn0), al1 = __expf(m1 - mn1);
        m0 = mn0; m1 = mn1;

        float s0 = 0.0f, s1 = 0.0f;
#pragma unroll
        for (int nt = 0; nt < 8; nt++) {
            float p00 = __expf(sacc[nt][0] - mn0);
            float p01 = __expf(sacc[nt][1] - mn0);
            float p10 = __expf(sacc[nt][2] - mn1);
            float p11 = __expf(sacc[nt][3] - mn1);
            s0 += p00 + p01;
            s1 += p10 + p11;
            float2 v0 = { rna_tf32(p00), rna_tf32(p01) };
            float2 v1 = { rna_tf32(p10), rna_tf32(p11) };
            *(float2*)&Pw[prow0 + nt * 8 + 2 * t] = v0;
            *(float2*)&Pw[prow1 + nt * 8 + 2 * t] = v1;
            oacc[nt][0] *= al0; oacc[nt][1] *= al0;
            oacc[nt][2] *= al1; oacc[nt][3] *= al1;
        }
        s0 += __shfl_xor_sync(0xffffffffu, s0, 1);
        s0 += __shfl_xor_sync(0xffffffffu, s0, 2);
        s1 += __shfl_xor_sync(0xffffffffu, s1, 1);
        s1 += __shfl_xor_sync(0xffffffffu, s1, 2);
        l0 = l0 * al0 + s0;
        l1 = l1 * al1 + s1;
        __syncwarp();   // P strip visible to all lanes of this warp

        // O += P @ V   (per warp: own 16 rows x 64 dims, k over 64 keys)
#pragma unroll
        for (int ks = 0; ks < 8; ks++) {
            const int kc = ks * 8;
            uint32_t a[4];
            int ra = prow0 + kc + t;
            a[0] = __float_as_uint(Pw[ra]);
            a[1] = __float_as_uint(Pw[ra + 8 * PS_STR]);
            a[2] = __float_as_uint(Pw[ra + 4]);
            a[3] = __float_as_uint(Pw[ra + 8 * PS_STR + 4]);
#pragma unroll
            for (int nt = 0; nt < 8; nt++) {
                uint32_t bb[2];
                bb[0] = __float_as_uint(Vs[(kc + t) * VS_STR + nt * 8 + g]);
                bb[1] = __float_as_uint(Vs[(kc + t + 4) * VS_STR + nt * 8 + g]);
                mma_tf32(oacc[nt], a, bb);
            }
        }
        __syncthreads();   // everyone done with buffer p (and P strip)
        if (kt + 2 < SEQ / KTL) load_kv(kt + 2, p);
        else asm volatile("cp.async.commit_group;");
    }

    // epilogue: normalize, rna-round (feeds tf32 out-projection), write [B,S,E]
    const float inv0 = 1.0f / l0, inv1 = 1.0f / l1;
    float* orow0 = out + (size_t)(b * SEQ + q0 + wid * 16 + g) * EMB + h * HDIM;
    float* orow1 = orow0 + (size_t)8 * EMB;
#pragma unroll
    for (int nt = 0; nt < 8; nt++) {
        const int col = nt * 8 + 2 * t;
        float2 v0 = { rna_tf32(oacc[nt][0] * inv0), rna_tf32(oacc[nt][1] * inv0) };
        float2 v1 = { rna_tf32(oacc[nt][2] * inv1), rna_tf32(oacc[nt][3] * inv1) };
        *(float2*)&orow0[col] = v0;
        *(float2*)&orow1[col] = v1;
    }
}

// ---------------------------------------------------------------------------
// launch
// ---------------------------------------------------------------------------
extern "C" void kernel_launch(void* const* d_in, const int* in_sizes, int n_in,
                              void* d_out, int out_size)
{
    const float* x     = (const float*)d_in[0];  // [2,2048,1024]
    const float* W_qkv = (const float*)d_in[1];  // [1024,3072]
    const float* b_qkv = (const float*)d_in[2];  // [3072]
    const float* W_out = (const float*)d_in[3];  // [1024,1024]
    const float* b_out = (const float*)d_in[4];  // [1024]
    float* out = (float*)d_out;                  // [2,2048,1024]

    float *qkv, *attn, *xc, *wqt, *wot;
    cudaGetSymbolAddress((void**)&qkv,  g_qkv);
    cudaGetSymbolAddress((void**)&attn, g_attn);
    cudaGetSymbolAddress((void**)&xc,   g_xc);
    cudaGetSymbolAddress((void**)&wqt,  g_wqt);
    cudaGetSymbolAddress((void**)&wot,  g_wot);

    // 0) prep: tf32-rna rounding of x, transposed+rounded weights
    cvt_rna_kernel<<<(ROWS * EMB / 4 + 255) / 256, 256>>>((const float4*)x, (float4*)xc, ROWS * EMB / 4);
    transpose_cvt_kernel<<<dim3(QKV_N / 32, EMB / 32), dim3(32, 8)>>>(W_qkv, wqt, EMB, QKV_N);
    transpose_cvt_kernel<<<dim3(EMB / 32, EMB / 32), dim3(32, 8)>>>(W_out, wot, EMB, EMB);

    cudaFuncSetAttribute(gemm_tc_kernel<true>,
                         cudaFuncAttributeMaxDynamicSharedMemorySize, GK_DSMEM);
    cudaFuncSetAttribute(gemm_tc_kernel<false>,
                         cudaFuncAttributeMaxDynamicSharedMemorySize, GK_DSMEM);
    cudaFuncSetAttribute(attn_tc_kernel,
                         cudaFuncAttributeMaxDynamicSharedMemorySize, ATTN_SMEM_BYTES);

    // 1) QKV projection (rounded output -> q,k,v are tf32 patterns)
    gemm_tc_kernel<true><<<dim3(QKV_N / 128, ROWS / 128), 256, GK_DSMEM>>>(
        xc, wqt, b_qkv, qkv, EMB, QKV_N);

    // 2) tensor-core flash attention
    attn_tc_kernel<<<dim3(SEQ / 128, NHEAD, BSZ), 256, ATTN_SMEM_BYTES>>>(qkv, attn);

    // 3) output projection (exact fp32 output)
    gemm_tc_kernel<false><<<dim3(EMB / 128, ROWS / 128), 256, GK_DSMEM>>>(
        attn, wot, b_out, out, EMB, EMB);
}

// round 7
// speedup vs baseline: 3.9119x; 1.0210x over previous
#include <cuda_runtime.h>
#include <cuda_bf16.h>
#include <math_constants.h>
#include <cstdint>

// Problem constants (fixed by reference): B=2, S=2048, E=1024, H=16, D=64
#define BSZ   2
#define SEQ   2048
#define EMB   1024
#define NHEAD 16
#define HDIM  64
#define ROWS  (BSZ * SEQ)          // 4096
#define QKV_N (3 * EMB)            // 3072

// Scratch (allocation-free rule: __device__ globals)
static __device__ float g_qkv[ROWS * QKV_N];    // [4096, 3072] (tf32-rounded)
static __device__ float g_attn[ROWS * EMB];     // [4096, 1024] (tf32-rounded)
static __device__ float g_xc[ROWS * EMB];       // x, tf32-rounded
static __device__ float g_wqt[QKV_N * EMB];     // W_qkv^T [3072,1024], tf32-rounded
static __device__ float g_wot[EMB * EMB];       // W_out^T [1024,1024], tf32-rounded

// ---------------------------------------------------------------------------
// helpers
// ---------------------------------------------------------------------------
__device__ __forceinline__ uint32_t smem_to_u32(const void* p) {
    uint32_t a;
    asm("{ .reg .u64 t; cvta.to.shared.u64 t, %1; cvt.u32.u64 %0, t; }" : "=r"(a) : "l"(p));
    return a;
}
// cvt.rna.tf32.f32 writes a .b32 destination (tf32 is a bit pattern)
__device__ __forceinline__ float rna_tf32(float x) {
    uint32_t r;
    asm("cvt.rna.tf32.f32 %0, %1;" : "=r"(r) : "f"(x));
    return __uint_as_float(r);
}
__device__ __forceinline__ void cp16(uint32_t d, const void* s) {
    asm volatile("cp.async.cg.shared.global [%0], [%1], 16;" :: "r"(d), "l"(s));
}
// warp-level tf32 MMA (sm_80+; works at compute_100)
__device__ __forceinline__ void mma_tf32(float* c, const uint32_t* a, const uint32_t* b) {
    asm volatile("mma.sync.aligned.m16n8k8.row.col.f32.tf32.tf32.f32 "
                 "{%0,%1,%2,%3}, {%4,%5,%6,%7}, {%8,%9}, {%0,%1,%2,%3};"
                 : "+f"(c[0]), "+f"(c[1]), "+f"(c[2]), "+f"(c[3])
                 : "r"(a[0]), "r"(a[1]), "r"(a[2]), "r"(a[3]),
                   "r"(b[0]), "r"(b[1]));
}

// ---------------------------------------------------------------------------
// Prep kernels: tf32-rna rounding (+ transpose for weights)
// ---------------------------------------------------------------------------
__global__ void cvt_rna_kernel(const float4* __restrict__ in, float4* __restrict__ out, int n4) {
    int i = blockIdx.x * blockDim.x + threadIdx.x;
    if (i < n4) {
        float4 v = in[i];
        v.x = rna_tf32(v.x); v.y = rna_tf32(v.y);
        v.z = rna_tf32(v.z); v.w = rna_tf32(v.w);
        out[i] = v;
    }
}

// in: [R,C] row-major  ->  out: [C,R] row-major, rna-rounded
__global__ void transpose_cvt_kernel(const float* __restrict__ in, float* __restrict__ out,
                                     int R, int C) {
    __shared__ float t[32][33];
    int c0 = blockIdx.x * 32, r0 = blockIdx.y * 32;
    int tx = threadIdx.x, ty = threadIdx.y;
#pragma unroll
    for (int i = 0; i < 32; i += 8)
        t[ty + i][tx] = in[(size_t)(r0 + ty + i) * C + c0 + tx];
    __syncthreads();
#pragma unroll
    for (int i = 0; i < 32; i += 8)
        out[(size_t)(c0 + ty + i) * R + r0 + tx] = rna_tf32(t[tx][ty + i]);
}

// ---------------------------------------------------------------------------
// tf32 warp-MMA GEMM + bias: C[M,N] = A[M,K] @ Bt[N,K]^T + bias[N]
// CTA tile 128x128, 8 warps (2x4), each warp 64x32 (4x4 m16n8k8 tiles).
// Fragment loads are LDS.128-vectorized via k-lane remap kappa(s,t,h)=8t+2s+h
// (k is a pure reduction: any bijection works if A and B frags agree).
// ROUND: rna-round the output (for tensors feeding later tf32 MMAs).
// ---------------------------------------------------------------------------
#define RS        36                       // smem row stride in floats
#define ASTG      (128 * RS)               // words per operand stage (4608)
#define STG_WORDS (2 * ASTG)               // A + B per stage (9216)
#define GK_DSMEM  (2 * STG_WORDS * 4)      // 73728 B

template <bool ROUND>
__global__ void __launch_bounds__(256, 2)
gemm_tc_kernel(const float* __restrict__ A, const float* __restrict__ Bt,
               const float* __restrict__ bias, float* __restrict__ C,
               int K, int N)
{
    extern __shared__ float sh[];
    const int tid = threadIdx.x;
    const int wid = tid >> 5, lane = tid & 31;
    const int g = lane >> 2, t = lane & 3;
    const int row0 = blockIdx.y * 128;
    const int col0 = blockIdx.x * 128;
    const int mbase = (wid & 1) * 64;
    const int nbase = (wid >> 1) * 32;
    const int NK = K / 32;
    const uint32_t sb = smem_to_u32(sh);

    auto load_stage = [&](int j, int p) {
        const float* Ab = A + (size_t)row0 * K + j * 32;
        const float* Bb = Bt + (size_t)col0 * K + j * 32;
        uint32_t abase = sb + p * (STG_WORDS * 4);
        uint32_t bbase = abase + ASTG * 4;
#pragma unroll
        for (int i = 0; i < 4; i++) {
            int c = tid + 256 * i;
            int row = c >> 3, c8 = c & 7;
            cp16(abase + row * (RS * 4) + c8 * 16, Ab + (size_t)row * K + c8 * 4);
            cp16(bbase + row * (RS * 4) + c8 * 16, Bb + (size_t)row * K + c8 * 4);
        }
        asm volatile("cp.async.commit_group;");
    };

    float acc[4][4][4];
#pragma unroll
    for (int mt = 0; mt < 4; mt++)
#pragma unroll
        for (int nt = 0; nt < 4; nt++)
#pragma unroll
            for (int i = 0; i < 4; i++) acc[mt][nt][i] = 0.0f;

    load_stage(0, 0);
    load_stage(1, 1);

    for (int j = 0; j < NK; j++) {
        const int p = j & 1;
        asm volatile("cp.async.wait_group 1;");
        __syncthreads();

        const float* As = sh + p * STG_WORDS;
        const float* Bs = As + ASTG;
#pragma unroll
        for (int half = 0; half < 2; half++) {
            // vectorized fragment loads: positions 8t+4*half .. +3
            float4 av[4][2], bv[4];
#pragma unroll
            for (int mt = 0; mt < 4; mt++) {
                int r = (mbase + mt * 16 + g) * RS + 8 * t + 4 * half;
                av[mt][0] = *(const float4*)&As[r];
                av[mt][1] = *(const float4*)&As[r + 8 * RS];
            }
#pragma unroll
            for (int nt = 0; nt < 4; nt++)
                bv[nt] = *(const float4*)&Bs[(nbase + nt * 8 + g) * RS + 8 * t + 4 * half];
#pragma unroll
            for (int sh2 = 0; sh2 < 2; sh2++) {
#pragma unroll
                for (int mt = 0; mt < 4; mt++) {
                    const float* a0 = (const float*)&av[mt][0];
                    const float* a1 = (const float*)&av[mt][1];
                    uint32_t a[4];
                    a[0] = __float_as_uint(a0[2 * sh2]);
                    a[1] = __float_as_uint(a1[2 * sh2]);
                    a[2] = __float_as_uint(a0[2 * sh2 + 1]);
                    a[3] = __float_as_uint(a1[2 * sh2 + 1]);
#pragma unroll
                    for (int nt = 0; nt < 4; nt++) {
                        const float* be = (const float*)&bv[nt];
                        uint32_t b[2];
                        b[0] = __float_as_uint(be[2 * sh2]);
                        b[1] = __float_as_uint(be[2 * sh2 + 1]);
                        mma_tf32(acc[mt][nt], a, b);
                    }
                }
            }
        }
        __syncthreads();
        if (j + 2 < NK) load_stage(j + 2, p);
        else asm volatile("cp.async.commit_group;");   // keep group count in step
    }

    // epilogue: c0/c1 -> (row, col..col+1), c2/c3 -> (row+8, ...)
#pragma unroll
    for (int mt = 0; mt < 4; mt++) {
        const int row = row0 + mbase + mt * 16 + g;
#pragma unroll
        for (int nt = 0; nt < 4; nt++) {
            const int col = col0 + nbase + nt * 8 + t * 2;
            const float b0 = bias[col], b1 = bias[col + 1];
            float2 v0, v1;
            if (ROUND) {
                v0 = { rna_tf32(acc[mt][nt][0] + b0), rna_tf32(acc[mt][nt][1] + b1) };
                v1 = { rna_tf32(acc[mt][nt][2] + b0), rna_tf32(acc[mt][nt][3] + b1) };
            } else {
                v0 = { acc[mt][nt][0] + b0, acc[mt][nt][1] + b1 };
                v1 = { acc[mt][nt][2] + b0, acc[mt][nt][3] + b1 };
            }
            *(float2*)&C[(size_t)row * N + col] = v0;
            *(float2*)&C[(size_t)(row + 8) * N + col] = v1;
        }
    }
}

// ---------------------------------------------------------------------------
// Tensor-core flash attention (non-causal, sm_scale = 1/8).
// CTA: 128 q-rows x one head; 8 warps, each owns 16 q-rows; 2 CTAs/SM.
// K-tile 64 keys, cp.async double-buffered. QK^T K-frags LDS.128-vectorized
// via kappa(s,t,h) = 32*(s/4) + 8t + 2*(s%4) + h (Q frags use same mapping).
// ---------------------------------------------------------------------------
#define KTL    64
#define KS_STR 68     // K frag LDS.128 bank pattern (4g+8t) mod 32: conflict-free
#define VS_STR 72     // V frag LDS pattern (8t+g) mod 32: conflict-free
#define PS_STR 68
#define SM_K0  0
#define SM_K1  (64 * KS_STR)
#define SM_V0  (2 * 64 * KS_STR)
#define SM_V1  (SM_V0 + 64 * VS_STR)
#define SM_P   (SM_V0 + 2 * 64 * VS_STR)
#define ATTN_SMEM_FLOATS (SM_P + 128 * PS_STR)
#define ATTN_SMEM_BYTES  (ATTN_SMEM_FLOATS * 4)    // 106496 B

__global__ void __launch_bounds__(256, 2)
attn_tc_kernel(const float* __restrict__ qkv, float* __restrict__ out)
{
    extern __shared__ float sh[];
    const uint32_t sb = smem_to_u32(sh);
    const int tid = threadIdx.x, wid = tid >> 5, lane = tid & 31;
    const int g = lane >> 2, t = lane & 3;
    const int h = blockIdx.y, b = blockIdx.z;
    const int q0 = blockIdx.x * 128;
    const size_t rowbase = (size_t)(b * SEQ) * QKV_N;
    const float* qbase = qkv + rowbase + (size_t)q0 * QKV_N + h * HDIM;

    // stage Q[128,64] into the P buffer, build register fragments
    {
#pragma unroll
        for (int i = 0; i < 8; i++) {
            int c = tid + 256 * i;              // 2048 float4 chunks
            int row = c >> 4, c16 = c & 15;
            cp16(sb + (SM_P + row * PS_STR) * 4 + c16 * 16,
                 qbase + (size_t)row * QKV_N + c16 * 4);
        }
        asm volatile("cp.async.commit_group;");
        asm volatile("cp.async.wait_group 0;");
        __syncthreads();
    }
    // Q fragments, indexed by kappa(s,t,h) = 32*(s/4) + 8t + 2*(s%4) + h
    uint32_t qf[8][4];
    {
        const float* Qs = sh + SM_P;
        const int r0 = (wid * 16 + g) * PS_STR;
#pragma unroll
        for (int s = 0; s < 8; s++) {
            int k0 = 32 * (s >> 2) + 8 * t + 2 * (s & 3);
            qf[s][0] = __float_as_uint(Qs[r0 + k0] * 0.125f);
            qf[s][1] = __float_as_uint(Qs[r0 + 8 * PS_STR + k0] * 0.125f);
            qf[s][2] = __float_as_uint(Qs[r0 + k0 + 1] * 0.125f);
            qf[s][3] = __float_as_uint(Qs[r0 + 8 * PS_STR + k0 + 1] * 0.125f);
        }
    }
    __syncthreads();

    float oacc[8][4];
#pragma unroll
    for (int nt = 0; nt < 8; nt++)
#pragma unroll
        for (int i = 0; i < 4; i++) oacc[nt][i] = 0.0f;
    float m0 = -CUDART_INF_F, m1 = -CUDART_INF_F, l0 = 0.0f, l1 = 0.0f;

    auto load_kv = [&](int kt2, int p) {
        const float* kb = qkv + rowbase + (size_t)(kt2 * KTL) * QKV_N + EMB + h * HDIM;
        const float* vb = kb + EMB;
        uint32_t kdst = sb + (p ? SM_K1 : SM_K0) * 4;
        uint32_t vdst = sb + (p ? SM_V1 : SM_V0) * 4;
#pragma unroll
        for (int i = 0; i < 4; i++) {
            int c = tid + 256 * i;              // 1024 float4 chunks each
            int row = c >> 4, c16 = c & 15;
            cp16(kdst + row * (KS_STR * 4) + c16 * 16, kb + (size_t)row * QKV_N + c16 * 4);
            cp16(vdst + row * (VS_STR * 4) + c16 * 16, vb + (size_t)row * QKV_N + c16 * 4);
        }
        asm volatile("cp.async.commit_group;");
    };

    load_kv(0, 0);
    load_kv(1, 1);

    float* Pw = sh + SM_P;
    const int prow0 = (wid * 16 + g) * PS_STR;
    const int prow1 = (wid * 16 + 8 + g) * PS_STR;

    for (int kt = 0; kt < SEQ / KTL; kt++) {
        const int p = kt & 1;
        asm volatile("cp.async.wait_group 1;");
        __syncthreads();
        const float* Ks = sh + (p ? SM_K1 : SM_K0);
        const float* Vs = sh + (p ? SM_V1 : SM_V0);

        // S = Q @ K^T  — K frags vectorized (LDS.128), nt in groups of 4
        float sacc[8][4];
#pragma unroll
        for (int nt = 0; nt < 8; nt++)
#pragma unroll
            for (int i = 0; i < 4; i++) sacc[nt][i] = 0.0f;
#pragma unroll
        for (int blk = 0; blk < 2; blk++)
#pragma unroll
        for (int hf = 0; hf < 2; hf++) {
            const int kc = 32 * blk + 8 * t + 4 * hf;
#pragma unroll
            for (int ng = 0; ng < 2; ng++) {
                float4 kv[4];
#pragma unroll
                for (int n4 = 0; n4 < 4; n4++)
                    kv[n4] = *(const float4*)&Ks[((ng * 4 + n4) * 8 + g) * KS_STR + kc];
#pragma unroll
                for (int sh2 = 0; sh2 < 2; sh2++) {
                    const int s = 4 * blk + 2 * hf + sh2;
#pragma unroll
                    for (int n4 = 0; n4 < 4; n4++) {
                        const float* be = (const float*)&kv[n4];
                        uint32_t bfrag[2];
                        bfrag[0] = __float_as_uint(be[2 * sh2]);
                        bfrag[1] = __float_as_uint(be[2 * sh2 + 1]);
                        mma_tf32(sacc[ng * 4 + n4], qf[s], bfrag);
                    }
                }
            }
        }

        // online softmax (rows g and g+8 of this warp's block)
        float mt0 = -CUDART_INF_F, mt1 = -CUDART_INF_F;
#pragma unroll
        for (int nt = 0; nt < 8; nt++) {
            mt0 = fmaxf(mt0, fmaxf(sacc[nt][0], sacc[nt][1]));
            mt1 = fmaxf(mt1, fmaxf(sacc[nt][2], sacc[nt][3]));
        }
        mt0 = fmaxf(mt0, __shfl_xor_sync(0xffffffffu, mt0, 1));
        mt0 = fmaxf(mt0, __shfl_xor_sync(0xffffffffu, mt0, 2));
        mt1 = fmaxf(mt1, __shfl_xor_sync(0xffffffffu, mt1, 1));
        mt1 = fmaxf(mt1, __shfl_xor_sync(0xffffffffu, mt1, 2));

        const float mn0 = fmaxf(m0, mt0), mn1 = fmaxf(m1, mt1);
        const float al0 = __expf(m0 - mn0), al1 = __expf(m1 - mn1);
        m0 = mn0; m1 = mn1;

        float s0 = 0.0f, s1 = 0.0f;
#pragma unroll
        for (int nt = 0; nt < 8; nt++) {
            float p00 = __expf(sacc[nt][0] - mn0);
            float p01 = __expf(sacc[nt][1] - mn0);
            float p10 = __expf(sacc[nt][2] - mn1);
            float p11 = __expf(sacc[nt][3] - mn1);
            s0 += p00 + p01;
            s1 += p10 + p11;
            float2 v0 = { rna_tf32(p00), rna_tf32(p01) };
            float2 v1 = { rna_tf32(p10), rna_tf32(p11) };
            *(float2*)&Pw[prow0 + nt * 8 + 2 * t] = v0;
            *(float2*)&Pw[prow1 + nt * 8 + 2 * t] = v1;
            oacc[nt][0] *= al0; oacc[nt][1] *= al0;
            oacc[nt][2] *= al1; oacc[nt][3] *= al1;
        }
        s0 += __shfl_xor_sync(0xffffffffu, s0, 1);
        s0 += __shfl_xor_sync(0xffffffffu, s0, 2);
        s1 += __shfl_xor_sync(0xffffffffu, s1, 1);
        s1 += __shfl_xor_sync(0xffffffffu, s1, 2);
        l0 = l0 * al0 + s0;
        l1 = l1 * al1 + s1;
        __syncwarp();   // P strip visible to all lanes of this warp

        // O += P @ V   (per warp: own 16 rows x 64 dims, k over 64 keys)
#pragma unroll
        for (int ks = 0; ks < 8; ks++) {
            const int kc = ks * 8;
            uint32_t a[4];
            int ra = prow0 + kc + t;
            a[0] = __float_as_uint(Pw[ra]);
            a[1] = __float_as_uint(Pw[ra + 8 * PS_STR]);
            a[2] = __float_as_uint(Pw[ra + 4]);
            a[3] = __float_as_uint(Pw[ra + 8 * PS_STR + 4]);
#pragma unroll
            for (int nt = 0; nt < 8; nt++) {
                uint32_t bb[2];
                bb[0] = __float_as_uint(Vs[(kc + t) * VS_STR + nt * 8 + g]);
                bb[1] = __float_as_uint(Vs[(kc + t + 4) * VS_STR + nt * 8 + g]);
                mma_tf32(oacc[nt], a, bb);
            }
        }
        __syncthreads();   // everyone done with buffer p (and P strip)
        if (kt + 2 < SEQ / KTL) load_kv(kt + 2, p);
        else asm volatile("cp.async.commit_group;");
    }

    // epilogue: normalize, rna-round (feeds tf32 out-projection), write [B,S,E]
    const float inv0 = 1.0f / l0, inv1 = 1.0f / l1;
    float* orow0 = out + (size_t)(b * SEQ + q0 + wid * 16 + g) * EMB + h * HDIM;
    float* orow1 = orow0 + (size_t)8 * EMB;
#pragma unroll
    for (int nt = 0; nt < 8; nt++) {
        const int col = nt * 8 + 2 * t;
        float2 v0 = { rna_tf32(oacc[nt][0] * inv0), rna_tf32(oacc[nt][1] * inv0) };
        float2 v1 = { rna_tf32(oacc[nt][2] * inv1), rna_tf32(oacc[nt][3] * inv1) };
        *(float2*)&orow0[col] = v0;
        *(float2*)&orow1[col] = v1;
    }
}

// ---------------------------------------------------------------------------
// launch
// ---------------------------------------------------------------------------
extern "C" void kernel_launch(void* const* d_in, const int* in_sizes, int n_in,
                              void* d_out, int out_size)
{
    const float* x     = (const float*)d_in[0];  // [2,2048,1024]
    const float* W_qkv = (const float*)d_in[1];  // [1024,3072]
    const float* b_qkv = (const float*)d_in[2];  // [3072]
    const float* W_out = (const float*)d_in[3];  // [1024,1024]
    const float* b_out = (const float*)d_in[4];  // [1024]
    float* out = (float*)d_out;                  // [2,2048,1024]

    float *qkv, *attn, *xc, *wqt, *wot;
    cudaGetSymbolAddress((void**)&qkv,  g_qkv);
    cudaGetSymbolAddress((void**)&attn, g_attn);
    cudaGetSymbolAddress((void**)&xc,   g_xc);
    cudaGetSymbolAddress((void**)&wqt,  g_wqt);
    cudaGetSymbolAddress((void**)&wot,  g_wot);

    // 0) prep: tf32-rna rounding of x, transposed+rounded weights
    cvt_rna_kernel<<<(ROWS * EMB / 4 + 255) / 256, 256>>>((const float4*)x, (float4*)xc, ROWS * EMB / 4);
    transpose_cvt_kernel<<<dim3(QKV_N / 32, EMB / 32), dim3(32, 8)>>>(W_qkv, wqt, EMB, QKV_N);
    transpose_cvt_kernel<<<dim3(EMB / 32, EMB / 32), dim3(32, 8)>>>(W_out, wot, EMB, EMB);

    cudaFuncSetAttribute(gemm_tc_kernel<true>,
                         cudaFuncAttributeMaxDynamicSharedMemorySize, GK_DSMEM);
    cudaFuncSetAttribute(gemm_tc_kernel<false>,
                         cudaFuncAttributeMaxDynamicSharedMemorySize, GK_DSMEM);
    cudaFuncSetAttribute(attn_tc_kernel,
                         cudaFuncAttributeMaxDynamicSharedMemorySize, ATTN_SMEM_BYTES);

    // 1) QKV projection (rounded output -> q,k,v are tf32 patterns)
    gemm_tc_kernel<true><<<dim3(QKV_N / 128, ROWS / 128), 256, GK_DSMEM>>>(
        xc, wqt, b_qkv, qkv, EMB, QKV_N);

    // 2) tensor-core flash attention
    attn_tc_kernel<<<dim3(SEQ / 128, NHEAD, BSZ), 256, ATTN_SMEM_BYTES>>>(qkv, attn);

    // 3) output projection (exact fp32 output)
    gemm_tc_kernel<false><<<dim3(EMB / 128, ROWS / 128), 256, GK_DSMEM>>>(
        attn, wot, b_out, out, EMB, EMB);
}

// round 9
// speedup vs baseline: 4.3197x; 1.1042x over previous
#include <cuda_runtime.h>
#include <cuda_bf16.h>
#include <math_constants.h>
#include <cstdint>

// Problem constants (fixed by reference): B=2, S=2048, E=1024, H=16, D=64
#define BSZ   2
#define SEQ   2048
#define EMB   1024
#define NHEAD 16
#define HDIM  64
#define ROWS  (BSZ * SEQ)          // 4096
#define QKV_N (3 * EMB)            // 3072

// Scratch (allocation-free rule: __device__ globals)
static __device__ float g_qkv[ROWS * QKV_N];    // [4096, 3072] (tf32-rounded)
static __device__ float g_attn[ROWS * EMB];     // [4096, 1024] (tf32-rounded)
static __device__ float g_xc[ROWS * EMB];       // x, tf32-rounded
static __device__ float g_wqt[QKV_N * EMB];     // W_qkv^T [3072,1024], tf32-rounded
static __device__ float g_wot[EMB * EMB];       // W_out^T [1024,1024], tf32-rounded

// ---------------------------------------------------------------------------
// helpers
// ---------------------------------------------------------------------------
__device__ __forceinline__ uint32_t smem_to_u32(const void* p) {
    uint32_t a;
    asm("{ .reg .u64 t; cvta.to.shared.u64 t, %1; cvt.u32.u64 %0, t; }" : "=r"(a) : "l"(p));
    return a;
}
// cvt.rna.tf32.f32 writes a .b32 destination (tf32 is a bit pattern)
__device__ __forceinline__ float rna_tf32(float x) {
    uint32_t r;
    asm("cvt.rna.tf32.f32 %0, %1;" : "=r"(r) : "f"(x));
    return __uint_as_float(r);
}
__device__ __forceinline__ void cp16(uint32_t d, const void* s) {
    asm volatile("cp.async.cg.shared.global [%0], [%1], 16;" :: "r"(d), "l"(s));
}
// warp-level tf32 MMA (sm_80+; works at compute_100)
__device__ __forceinline__ void mma_tf32(float* c, const uint32_t* a, const uint32_t* b) {
    asm volatile("mma.sync.aligned.m16n8k8.row.col.f32.tf32.tf32.f32 "
                 "{%0,%1,%2,%3}, {%4,%5,%6,%7}, {%8,%9}, {%0,%1,%2,%3};"
                 : "+f"(c[0]), "+f"(c[1]), "+f"(c[2]), "+f"(c[3])
                 : "r"(a[0]), "r"(a[1]), "r"(a[2]), "r"(a[3]),
                   "r"(b[0]), "r"(b[1]));
}

// ---------------------------------------------------------------------------
// Prep kernels: tf32-rna rounding (+ transpose for weights)
// ---------------------------------------------------------------------------
__global__ void cvt_rna_kernel(const float4* __restrict__ in, float4* __restrict__ out, int n4) {
    int i = blockIdx.x * blockDim.x + threadIdx.x;
    if (i < n4) {
        float4 v = in[i];
        v.x = rna_tf32(v.x); v.y = rna_tf32(v.y);
        v.z = rna_tf32(v.z); v.w = rna_tf32(v.w);
        out[i] = v;
    }
}

// in: [R,C] row-major  ->  out: [C,R] row-major, rna-rounded
__global__ void transpose_cvt_kernel(const float* __restrict__ in, float* __restrict__ out,
                                     int R, int C) {
    __shared__ float t[32][33];
    int c0 = blockIdx.x * 32, r0 = blockIdx.y * 32;
    int tx = threadIdx.x, ty = threadIdx.y;
#pragma unroll
    for (int i = 0; i < 32; i += 8)
        t[ty + i][tx] = in[(size_t)(r0 + ty + i) * C + c0 + tx];
    __syncthreads();
#pragma unroll
    for (int i = 0; i < 32; i += 8)
        out[(size_t)(c0 + ty + i) * R + r0 + tx] = rna_tf32(t[tx][ty + i]);
}

// ---------------------------------------------------------------------------
// tf32 warp-MMA GEMM + bias: C[M,N] = A[M,K] @ Bt[N,K]^T + bias[N]
// CTA tile 128x128, 8 warps (2x4), each warp 64x32 (4x4 m16n8k8 tiles).
// Scalar fragment loads (round-6 proven: 203us, tensor 46.9% — the float4
// variant regressed to 220us from register-unpack ALU/FMA traffic).
// ROUND: rna-round the output (for tensors feeding later tf32 MMAs).
// ---------------------------------------------------------------------------
#define RS        36                       // smem row stride in floats
#define ASTG      (128 * RS)               // words per operand stage (4608)
#define STG_WORDS (2 * ASTG)               // A + B per stage (9216)
#define GK_DSMEM  (2 * STG_WORDS * 4)      // 73728 B

template <bool ROUND>
__global__ void __launch_bounds__(256, 2)
gemm_tc_kernel(const float* __restrict__ A, const float* __restrict__ Bt,
               const float* __restrict__ bias, float* __restrict__ C,
               int K, int N)
{
    extern __shared__ float sh[];
    const int tid = threadIdx.x;
    const int wid = tid >> 5, lane = tid & 31;
    const int g = lane >> 2, t = lane & 3;
    const int row0 = blockIdx.y * 128;
    const int col0 = blockIdx.x * 128;
    const int mbase = (wid & 1) * 64;
    const int nbase = (wid >> 1) * 32;
    const int NK = K / 32;
    const uint32_t sb = smem_to_u32(sh);

    auto load_stage = [&](int j, int p) {
        const float* Ab = A + (size_t)row0 * K + j * 32;
        const float* Bb = Bt + (size_t)col0 * K + j * 32;
        uint32_t abase = sb + p * (STG_WORDS * 4);
        uint32_t bbase = abase + ASTG * 4;
#pragma unroll
        for (int i = 0; i < 4; i++) {
            int c = tid + 256 * i;
            int row = c >> 3, c8 = c & 7;
            cp16(abase + row * (RS * 4) + c8 * 16, Ab + (size_t)row * K + c8 * 4);
            cp16(bbase + row * (RS * 4) + c8 * 16, Bb + (size_t)row * K + c8 * 4);
        }
        asm volatile("cp.async.commit_group;");
    };

    float acc[4][4][4];
#pragma unroll
    for (int mt = 0; mt < 4; mt++)
#pragma unroll
        for (int nt = 0; nt < 4; nt++)
#pragma unroll
            for (int i = 0; i < 4; i++) acc[mt][nt][i] = 0.0f;

    load_stage(0, 0);
    load_stage(1, 1);

    for (int j = 0; j < NK; j++) {
        const int p = j & 1;
        asm volatile("cp.async.wait_group 1;");
        __syncthreads();

        const float* As = sh + p * STG_WORDS;
        const float* Bs = As + ASTG;
#pragma unroll
        for (int ks = 0; ks < 4; ks++) {
            const int kc = ks * 8;
            uint32_t a[4][4], b[4][2];
#pragma unroll
            for (int mt = 0; mt < 4; mt++) {
                int r0 = (mbase + mt * 16 + g) * RS + kc + t;
                a[mt][0] = __float_as_uint(As[r0]);
                a[mt][1] = __float_as_uint(As[r0 + 8 * RS]);
                a[mt][2] = __float_as_uint(As[r0 + 4]);
                a[mt][3] = __float_as_uint(As[r0 + 8 * RS + 4]);
            }
#pragma unroll
            for (int nt = 0; nt < 4; nt++) {
                int r0 = (nbase + nt * 8 + g) * RS + kc + t;
                b[nt][0] = __float_as_uint(Bs[r0]);
                b[nt][1] = __float_as_uint(Bs[r0 + 4]);
            }
#pragma unroll
            for (int mt = 0; mt < 4; mt++)
#pragma unroll
                for (int nt = 0; nt < 4; nt++)
                    mma_tf32(acc[mt][nt], a[mt], b[nt]);
        }
        __syncthreads();
        if (j + 2 < NK) load_stage(j + 2, p);
        else asm volatile("cp.async.commit_group;");   // keep group count in step
    }

    // epilogue: c0/c1 -> (row, col..col+1), c2/c3 -> (row+8, ...)
#pragma unroll
    for (int mt = 0; mt < 4; mt++) {
        const int row = row0 + mbase + mt * 16 + g;
#pragma unroll
        for (int nt = 0; nt < 4; nt++) {
            const int col = col0 + nbase + nt * 8 + t * 2;
            const float b0 = bias[col], b1 = bias[col + 1];
            float2 v0, v1;
            if (ROUND) {
                v0 = { rna_tf32(acc[mt][nt][0] + b0), rna_tf32(acc[mt][nt][1] + b1) };
                v1 = { rna_tf32(acc[mt][nt][2] + b0), rna_tf32(acc[mt][nt][3] + b1) };
            } else {
                v0 = { acc[mt][nt][0] + b0, acc[mt][nt][1] + b1 };
                v1 = { acc[mt][nt][2] + b0, acc[mt][nt][3] + b1 };
            }
            *(float2*)&C[(size_t)row * N + col] = v0;
            *(float2*)&C[(size_t)(row + 8) * N + col] = v1;
        }
    }
}

// ---------------------------------------------------------------------------
// Tensor-core flash attention (non-causal, sm_scale = 1/8).
// CTA: 128 q-rows x one head; 8 warps, each owns 16 q-rows; 2 CTAs/SM.
// K-tile 64 keys, cp.async double-buffered.
// QK^T: K-frags LDS.128-vectorized via k-remap kappa(s,t,h)=32(s/4)+8t+2(s%4)+h.
// P.V:  NO smem round-trip for P — the PV k-dim is remapped so that step s
//       consumes keys {8s+2t, 8s+2t+1}, exactly the softmax output registers
//       sacc[s]. V B-frag reads V[8s+2t][col], V[8s+2t+1][col]; VS_STR=68
//       makes the bank pattern (8t+g) mod 32: conflict-free.
// ---------------------------------------------------------------------------
#define KTL    64
#define KS_STR 68     // K frag LDS.128: quarter-warp phases hit disjoint bank groups
#define VS_STR 68     // V LDS.32 bank pattern (8t+g) mod 32: conflict-free
#define PS_STR 68     // Q staging
#define SM_K0  0
#define SM_K1  (64 * KS_STR)
#define SM_V0  (2 * 64 * KS_STR)
#define SM_V1  (SM_V0 + 64 * VS_STR)
#define SM_Q   (SM_V0 + 2 * 64 * VS_STR)
#define ATTN_SMEM_FLOATS (SM_Q + 128 * PS_STR)
#define ATTN_SMEM_BYTES  (ATTN_SMEM_FLOATS * 4)

__global__ void __launch_bounds__(256, 2)
attn_tc_kernel(const float* __restrict__ qkv, float* __restrict__ out)
{
    extern __shared__ float sh[];
    const uint32_t sb = smem_to_u32(sh);
    const int tid = threadIdx.x, wid = tid >> 5, lane = tid & 31;
    const int g = lane >> 2, t = lane & 3;
    const int h = blockIdx.y, b = blockIdx.z;
    const int q0 = blockIdx.x * 128;
    const size_t rowbase = (size_t)(b * SEQ) * QKV_N;
    const float* qbase = qkv + rowbase + (size_t)q0 * QKV_N + h * HDIM;

    // stage Q[128,64], build register fragments
    {
#pragma unroll
        for (int i = 0; i < 8; i++) {
            int c = tid + 256 * i;              // 2048 float4 chunks
            int row = c >> 4, c16 = c & 15;
            cp16(sb + (SM_Q + row * PS_STR) * 4 + c16 * 16,
                 qbase + (size_t)row * QKV_N + c16 * 4);
        }
        asm volatile("cp.async.commit_group;");
        asm volatile("cp.async.wait_group 0;");
        __syncthreads();
    }
    // Q fragments, indexed by kappa(s,t,h) = 32*(s/4) + 8t + 2*(s%4) + h
    uint32_t qf[8][4];
    {
        const float* Qs = sh + SM_Q;
        const int r0 = (wid * 16 + g) * PS_STR;
#pragma unroll
        for (int s = 0; s < 8; s++) {
            int k0 = 32 * (s >> 2) + 8 * t + 2 * (s & 3);
            qf[s][0] = __float_as_uint(Qs[r0 + k0] * 0.125f);
            qf[s][1] = __float_as_uint(Qs[r0 + 8 * PS_STR + k0] * 0.125f);
            qf[s][2] = __float_as_uint(Qs[r0 + k0 + 1] * 0.125f);
            qf[s][3] = __float_as_uint(Qs[r0 + 8 * PS_STR + k0 + 1] * 0.125f);
        }
    }
    __syncthreads();

    float oacc[8][4];
#pragma unroll
    for (int nt = 0; nt < 8; nt++)
#pragma unroll
        for (int i = 0; i < 4; i++) oacc[nt][i] = 0.0f;
    float m0 = -CUDART_INF_F, m1 = -CUDART_INF_F, l0 = 0.0f, l1 = 0.0f;

    auto load_kv = [&](int kt2, int p) {
        const float* kb = qkv + rowbase + (size_t)(kt2 * KTL) * QKV_N + EMB + h * HDIM;
        const float* vb = kb + EMB;
        uint32_t kdst = sb + (p ? SM_K1 : SM_K0) * 4;
        uint32_t vdst = sb + (p ? SM_V1 : SM_V0) * 4;
#pragma unroll
        for (int i = 0; i < 4; i++) {
            int c = tid + 256 * i;              // 1024 float4 chunks each
            int row = c >> 4, c16 = c & 15;
            cp16(kdst + row * (KS_STR * 4) + c16 * 16, kb + (size_t)row * QKV_N + c16 * 4);
            cp16(vdst + row * (VS_STR * 4) + c16 * 16, vb + (size_t)row * QKV_N + c16 * 4);
        }
        asm volatile("cp.async.commit_group;");
    };

    load_kv(0, 0);
    load_kv(1, 1);

    for (int kt = 0; kt < SEQ / KTL; kt++) {
        const int p = kt & 1;
        asm volatile("cp.async.wait_group 1;");
        __syncthreads();
        const float* Ks = sh + (p ? SM_K1 : SM_K0);
        const float* Vs = sh + (p ? SM_V1 : SM_V0);

        // S = Q @ K^T  — K frags vectorized (LDS.128), nt in groups of 4
        float sacc[8][4];
#pragma unroll
        for (int nt = 0; nt < 8; nt++)
#pragma unroll
            for (int i = 0; i < 4; i++) sacc[nt][i] = 0.0f;
#pragma unroll
        for (int blk = 0; blk < 2; blk++)
#pragma unroll
        for (int hf = 0; hf < 2; hf++) {
            const int kc = 32 * blk + 8 * t + 4 * hf;
#pragma unroll
            for (int ng = 0; ng < 2; ng++) {
                float4 kv[4];
#pragma unroll
                for (int n4 = 0; n4 < 4; n4++)
                    kv[n4] = *(const float4*)&Ks[((ng * 4 + n4) * 8 + g) * KS_STR + kc];
#pragma unroll
                for (int sh2 = 0; sh2 < 2; sh2++) {
                    const int s = 4 * blk + 2 * hf + sh2;
#pragma unroll
                    for (int n4 = 0; n4 < 4; n4++) {
                        const float* be = (const float*)&kv[n4];
                        uint32_t bfrag[2];
                        bfrag[0] = __float_as_uint(be[2 * sh2]);
                        bfrag[1] = __float_as_uint(be[2 * sh2 + 1]);
                        mma_tf32(sacc[ng * 4 + n4], qf[s], bfrag);
                    }
                }
            }
        }

        // online softmax (rows g and g+8 of this warp's block)
        float mt0 = -CUDART_INF_F, mt1 = -CUDART_INF_F;
#pragma unroll
        for (int nt = 0; nt < 8; nt++) {
            mt0 = fmaxf(mt0, fmaxf(sacc[nt][0], sacc[nt][1]));
            mt1 = fmaxf(mt1, fmaxf(sacc[nt][2], sacc[nt][3]));
        }
        mt0 = fmaxf(mt0, __shfl_xor_sync(0xffffffffu, mt0, 1));
        mt0 = fmaxf(mt0, __shfl_xor_sync(0xffffffffu, mt0, 2));
        mt1 = fmaxf(mt1, __shfl_xor_sync(0xffffffffu, mt1, 1));
        mt1 = fmaxf(mt1, __shfl_xor_sync(0xffffffffu, mt1, 2));

        const float mn0 = fmaxf(m0, mt0), mn1 = fmaxf(m1, mt1);
        const float al0 = __expf(m0 - mn0), al1 = __expf(m1 - mn1);
        m0 = mn0; m1 = mn1;

        float s0 = 0.0f, s1 = 0.0f;
#pragma unroll
        for (int nt = 0; nt < 8; nt++) {
            float p00 = __expf(sacc[nt][0] - mn0);
            float p01 = __expf(sacc[nt][1] - mn0);
            float p10 = __expf(sacc[nt][2] - mn1);
            float p11 = __expf(sacc[nt][3] - mn1);
            s0 += p00 + p01;
            s1 += p10 + p11;
            // keep rounded P in registers — they ARE the PV A-fragments
            sacc[nt][0] = rna_tf32(p00);
            sacc[nt][1] = rna_tf32(p01);
            sacc[nt][2] = rna_tf32(p10);
            sacc[nt][3] = rna_tf32(p11);
            oacc[nt][0] *= al0; oacc[nt][1] *= al0;
            oacc[nt][2] *= al1; oacc[nt][3] *= al1;
        }
        s0 += __shfl_xor_sync(0xffffffffu, s0, 1);
        s0 += __shfl_xor_sync(0xffffffffu, s0, 2);
        s1 += __shfl_xor_sync(0xffffffffu, s1, 1);
        s1 += __shfl_xor_sync(0xffffffffu, s1, 2);
        l0 = l0 * al0 + s0;
        l1 = l1 * al1 + s1;

        // O += P @ V — register-direct: step s consumes keys {8s+2t, 8s+2t+1},
        // A-frag = sacc[s] (a0=P[g][k0], a1=P[g+8][k0], a2=P[g][k1], a3=P[g+8][k1])
#pragma unroll
        for (int s = 0; s < 8; s++) {
            uint32_t a[4];
            a[0] = __float_as_uint(sacc[s][0]);
            a[1] = __float_as_uint(sacc[s][2]);
            a[2] = __float_as_uint(sacc[s][1]);
            a[3] = __float_as_uint(sacc[s][3]);
            const int k0 = (8 * s + 2 * t) * VS_STR;
#pragma unroll
            for (int ot = 0; ot < 8; ot++) {
                uint32_t bb[2];
                bb[0] = __float_as_uint(Vs[k0 + ot * 8 + g]);
                bb[1] = __float_as_uint(Vs[k0 + VS_STR + ot * 8 + g]);
                mma_tf32(oacc[ot], a, bb);
            }
        }
        __syncthreads();   // everyone done with buffer p
        if (kt + 2 < SEQ / KTL) load_kv(kt + 2, p);
        else asm volatile("cp.async.commit_group;");
    }

    // epilogue: normalize, rna-round (feeds tf32 out-projection), write [B,S,E]
    const float inv0 = 1.0f / l0, inv1 = 1.0f / l1;
    float* orow0 = out + (size_t)(b * SEQ + q0 + wid * 16 + g) * EMB + h * HDIM;
    float* orow1 = orow0 + (size_t)8 * EMB;
#pragma unroll
    for (int nt = 0; nt < 8; nt++) {
        const int col = nt * 8 + 2 * t;
        float2 v0 = { rna_tf32(oacc[nt][0] * inv0), rna_tf32(oacc[nt][1] * inv0) };
        float2 v1 = { rna_tf32(oacc[nt][2] * inv1), rna_tf32(oacc[nt][3] * inv1) };
        *(float2*)&orow0[col] = v0;
        *(float2*)&orow1[col] = v1;
    }
}

// ---------------------------------------------------------------------------
// launch
// ---------------------------------------------------------------------------
extern "C" void kernel_launch(void* const* d_in, const int* in_sizes, int n_in,
                              void* d_out, int out_size)
{
    const float* x     = (const float*)d_in[0];  // [2,2048,1024]
    const float* W_qkv = (const float*)d_in[1];  // [1024,3072]
    const float* b_qkv = (const float*)d_in[2];  // [3072]
    const float* W_out = (const float*)d_in[3];  // [1024,1024]
    const float* b_out = (const float*)d_in[4];  // [1024]
    float* out = (float*)d_out;                  // [2,2048,1024]

    float *qkv, *attn, *xc, *wqt, *wot;
    cudaGetSymbolAddress((void**)&qkv,  g_qkv);
    cudaGetSymbolAddress((void**)&attn, g_attn);
    cudaGetSymbolAddress((void**)&xc,   g_xc);
    cudaGetSymbolAddress((void**)&wqt,  g_wqt);
    cudaGetSymbolAddress((void**)&wot,  g_wot);

    // 0) prep: tf32-rna rounding of x, transposed+rounded weights
    cvt_rna_kernel<<<(ROWS * EMB / 4 + 255) / 256, 256>>>((const float4*)x, (float4*)xc, ROWS * EMB / 4);
    transpose_cvt_kernel<<<dim3(QKV_N / 32, EMB / 32), dim3(32, 8)>>>(W_qkv, wqt, EMB, QKV_N);
    transpose_cvt_kernel<<<dim3(EMB / 32, EMB / 32), dim3(32, 8)>>>(W_out, wot, EMB, EMB);

    cudaFuncSetAttribute(gemm_tc_kernel<true>,
                         cudaFuncAttributeMaxDynamicSharedMemorySize, GK_DSMEM);
    cudaFuncSetAttribute(gemm_tc_kernel<false>,
                         cudaFuncAttributeMaxDynamicSharedMemorySize, GK_DSMEM);
    cudaFuncSetAttribute(attn_tc_kernel,
                         cudaFuncAttributeMaxDynamicSharedMemorySize, ATTN_SMEM_BYTES);

    // 1) QKV projection (rounded output -> q,k,v are tf32 patterns)
    gemm_tc_kernel<true><<<dim3(QKV_N / 128, ROWS / 128), 256, GK_DSMEM>>>(
        xc, wqt, b_qkv, qkv, EMB, QKV_N);

    // 2) tensor-core flash attention
    attn_tc_kernel<<<dim3(SEQ / 128, NHEAD, BSZ), 256, ATTN_SMEM_BYTES>>>(qkv, attn);

    // 3) output projection (exact fp32 output)
    gemm_tc_kernel<false><<<dim3(EMB / 128, ROWS / 128), 256, GK_DSMEM>>>(
        attn, wot, b_out, out, EMB, EMB);
}